// round 8
// baseline (speedup 1.0000x reference)
#include <cuda_runtime.h>
#include <cuda_bf16.h>
#include <stdint.h>
#include <math.h>

// LSTM: B=64, T=256, I=512, H=1024 -> out[b,t,h] fp32
//
// Per step t: gates^T D[gc, r] = sum_k Wt[gc][k] * act[r][k],  K = 1536,
// Wt = [Wh;Wx]^T gate-interleaved (gc = 4j+q), act = [h_t | x_t].
// Precision: bf16 2-term split (hi+lo), 3 HMMA products, fp32 accum.
//
// ONE kernel per step: grid (32 Mtiles x 4 K-splits). Each CTA computes its
// 128gc x 64r partial (3-stage cp.async pipeline, mma.sync m16n8k16.bf16),
// stores partials with st.cg, then last-arriving CTA per Mtile (fenced
// atomic counter, per-(t,Mtile) slot) reduces the 4 partials IN FIXED ORDER
// (deterministic) and applies the fused LSTM cell: writes out, c (ld/st.cg),
// and re-split h into the (t+1)&1 buffer (h double-buffered because other
// CTAs of step t may still be reading h_t).

#define Bn 64
#define Tn 256
#define In 512
#define Hn 1024
#define Gn 4096
#define Kt 1536
#define NCH 4
#define KCH 384
#define BK 64
#define NCHUNK 6

#define ST_WH 0
#define ST_WL 16384
#define ST_AH 32768
#define ST_AL 40960
#define STAGE_BYTES 49152
#define NSTAGE 3
#define SMEM_TOTAL (NSTAGE * STAGE_BYTES)

#define SWZ(o) ((o) ^ (((o) >> 3) & 0x70))

static __device__ __nv_bfloat16 g_Whi[(size_t)Gn * Kt];
static __device__ __nv_bfloat16 g_Wlo[(size_t)Gn * Kt];
static __device__ __nv_bfloat16 g_xhi[(size_t)Bn * Tn * In];
static __device__ __nv_bfloat16 g_xlo[(size_t)Bn * Tn * In];
static __device__ __nv_bfloat16 g_hhi[2 * Bn * Hn];      // double-buffered
static __device__ __nv_bfloat16 g_hlo[2 * Bn * Hn];
static __device__ float g_c[Bn * Hn];
static __device__ float g_bp[Gn];
static __device__ float g_part[(size_t)NCH * Gn * Bn];   // [ch][gc][r]
static __device__ unsigned g_cnt[Tn * 32];               // per (t, Mtile)

// ---------------------------------------------------------------------------
__device__ __forceinline__ uint32_t smem_u32(const void* p) {
    uint32_t a;
    asm("{ .reg .u64 t; cvta.to.shared.u64 t, %1; cvt.u32.u64 %0, t; }"
        : "=r"(a) : "l"(p));
    return a;
}
__device__ __forceinline__ void cpa16(uint32_t dst, const void* src) {
    asm volatile("cp.async.cg.shared.global [%0], [%1], 16;"
                 :: "r"(dst), "l"(src));
}
#define CP_COMMIT() asm volatile("cp.async.commit_group;" ::: "memory")
#define CP_WAIT(n)  asm volatile("cp.async.wait_group %0;" :: "n"(n) : "memory")

__device__ __forceinline__ void ldm_x4(uint32_t a, uint32_t r[4]) {
    asm volatile("ldmatrix.sync.aligned.m8n8.x4.shared.b16 {%0,%1,%2,%3}, [%4];"
                 : "=r"(r[0]), "=r"(r[1]), "=r"(r[2]), "=r"(r[3]) : "r"(a));
}
__device__ __forceinline__ void mma16816(float acc[4], const uint32_t a[4],
                                         uint32_t b0, uint32_t b1) {
    asm volatile(
        "mma.sync.aligned.m16n8k16.row.col.f32.bf16.bf16.f32 "
        "{%0,%1,%2,%3}, {%4,%5,%6,%7}, {%8,%9}, {%0,%1,%2,%3};"
        : "+f"(acc[0]), "+f"(acc[1]), "+f"(acc[2]), "+f"(acc[3])
        : "r"(a[0]), "r"(a[1]), "r"(a[2]), "r"(a[3]), "r"(b0), "r"(b1));
}

// ---------------------------------------------------------------------------
__global__ void wprep_kernel(const float* __restrict__ Wx,
                             const float* __restrict__ Wh,
                             const float* __restrict__ b) {
    int gc = blockIdx.x;
    int k  = blockIdx.y * 256 + threadIdx.x;
    int j = gc >> 2, q = gc & 3;
    int src = q * Hn + j;
    float w = (k < Hn) ? Wh[(size_t)k * Gn + src]
                       : Wx[(size_t)(k - Hn) * Gn + src];
    __nv_bfloat16 hi = __float2bfloat16(w);
    g_Whi[(size_t)gc * Kt + k] = hi;
    g_Wlo[(size_t)gc * Kt + k] = __float2bfloat16(w - __bfloat162float(hi));
    if (k == 0) g_bp[gc] = b[src];
}

// ---------------------------------------------------------------------------
__global__ void xprep_kernel(const float* __restrict__ x) {
    int idx = blockIdx.x * 1024 + threadIdx.x;
    float v = x[idx];
    __nv_bfloat16 hi = __float2bfloat16(v);
    g_xhi[idx] = hi;
    g_xlo[idx] = __float2bfloat16(v - __bfloat162float(hi));
    if (idx < Bn * Hn) {
        g_c[idx] = 0.0f;
        __nv_bfloat16 z = __float2bfloat16(0.0f);
        g_hhi[idx] = z;  g_hhi[Bn * Hn + idx] = z;
        g_hlo[idx] = z;  g_hlo[Bn * Hn + idx] = z;
    }
    if (idx < Tn * 32) g_cnt[idx] = 0u;
}

// ---------------------------------------------------------------------------
__global__ __launch_bounds__(256, 1)
void gemm_kernel(int t, float* __restrict__ out) {
    extern __shared__ char smem[];
    const uint32_t sb = smem_u32(smem);

    const int tid   = threadIdx.x;
    const int lane  = tid & 31;
    const int warp  = tid >> 5;
    const int wr    = warp & 3;
    const int wc    = warp >> 2;
    const int Mtile = blockIdx.x;
    const int ch    = blockIdx.y;
    const int kBase = ch * KCH;

    const __nv_bfloat16* __restrict__ hhi = g_hhi + (size_t)(t & 1) * (Bn * Hn);
    const __nv_bfloat16* __restrict__ hlo = g_hlo + (size_t)(t & 1) * (Bn * Hn);

    auto load_stage = [&](int c) {
        const uint32_t st = sb + (uint32_t)(c % NSTAGE) * STAGE_BYTES;
        const int k0 = kBase + c * BK;
#pragma unroll
        for (int i = 0; i < 4; i++) {
            int l = tid + 256 * i;
            int row = l >> 3;
            int kq = (l & 7) << 3;
            uint32_t off = SWZ((uint32_t)(row * 128 + kq * 2));
            size_t ga = (size_t)(Mtile * 128 + row) * Kt + k0 + kq;
            cpa16(st + ST_WH + off, g_Whi + ga);
            cpa16(st + ST_WL + off, g_Wlo + ga);
        }
#pragma unroll
        for (int i = 0; i < 2; i++) {
            int l = tid + 256 * i;
            int row = l >> 3;
            int kq = (l & 7) << 3;
            uint32_t off = SWZ((uint32_t)(row * 128 + kq * 2));
            int k = k0 + kq;
            const __nv_bfloat16 *ph, *pl;
            if (k < Hn) {
                ph = hhi + row * Hn + k;
                pl = hlo + row * Hn + k;
            } else {
                size_t xo = ((size_t)row * Tn + t) * In + (k - Hn);
                ph = g_xhi + xo;
                pl = g_xlo + xo;
            }
            cpa16(st + ST_AH + off, ph);
            cpa16(st + ST_AL + off, pl);
        }
        CP_COMMIT();
    };

    float acc[2][4][4];
#pragma unroll
    for (int mt = 0; mt < 2; mt++)
#pragma unroll
        for (int nt = 0; nt < 4; nt++)
#pragma unroll
            for (int e = 0; e < 4; e++) acc[mt][nt][e] = 0.0f;

    const int lm_m = lane >> 3;
    const int lm_r = lane & 7;

    load_stage(0);
    load_stage(1);

#pragma unroll
    for (int c = 0; c < NCHUNK; c++) {
        if (c + 2 < NCHUNK) load_stage(c + 2);
        if (c < NCHUNK - 2)      { CP_WAIT(2); }
        else if (c == NCHUNK - 2){ CP_WAIT(1); }
        else                     { CP_WAIT(0); }
        __syncthreads();

        const uint32_t st = sb + (uint32_t)(c % NSTAGE) * STAGE_BYTES;

#pragma unroll
        for (int ks = 0; ks < 4; ks++) {
            const int kc = ks * 16;
            uint32_t ah[2][4], al[2][4];
#pragma unroll
            for (int mt = 0; mt < 2; mt++) {
                int row = wr * 32 + mt * 16 + (lm_m & 1) * 8 + lm_r;
                int kcol = kc + (lm_m >> 1) * 8;
                uint32_t off = SWZ((uint32_t)(row * 128 + kcol * 2));
                ldm_x4(st + ST_WH + off, ah[mt]);
                ldm_x4(st + ST_WL + off, al[mt]);
            }
            uint32_t bh[4][2], bl[4][2];
#pragma unroll
            for (int np = 0; np < 2; np++) {
                int nrow = wc * 32 + np * 16 + (lm_m >> 1) * 8 + lm_r;
                int kcol = kc + (lm_m & 1) * 8;
                uint32_t off = SWZ((uint32_t)(nrow * 128 + kcol * 2));
                uint32_t rh[4], rl[4];
                ldm_x4(st + ST_AH + off, rh);
                ldm_x4(st + ST_AL + off, rl);
                bh[2 * np][0] = rh[0]; bh[2 * np][1] = rh[1];
                bh[2 * np + 1][0] = rh[2]; bh[2 * np + 1][1] = rh[3];
                bl[2 * np][0] = rl[0]; bl[2 * np][1] = rl[1];
                bl[2 * np + 1][0] = rl[2]; bl[2 * np + 1][1] = rl[3];
            }
#pragma unroll
            for (int mt = 0; mt < 2; mt++)
#pragma unroll
                for (int nt = 0; nt < 4; nt++) {
                    mma16816(acc[mt][nt], ah[mt], bh[nt][0], bh[nt][1]);
                    mma16816(acc[mt][nt], ah[mt], bl[nt][0], bl[nt][1]);
                    mma16816(acc[mt][nt], al[mt], bh[nt][0], bh[nt][1]);
                }
        }
        __syncthreads();
    }

    // ---- store partials (L2-coherent; g_part reused every step) ----
    const int dg = lane >> 2;
    const int dt = lane & 3;
#pragma unroll
    for (int mt = 0; mt < 2; mt++)
#pragma unroll
        for (int nt = 0; nt < 4; nt++) {
            int gc0 = Mtile * 128 + wr * 32 + mt * 16 + dg;
            int r0  = wc * 32 + nt * 8 + 2 * dt;
            __stcg((float2*)(g_part + ((size_t)ch * Gn + gc0) * Bn + r0),
                   make_float2(acc[mt][nt][0], acc[mt][nt][1]));
            __stcg((float2*)(g_part + ((size_t)ch * Gn + gc0 + 8) * Bn + r0),
                   make_float2(acc[mt][nt][2], acc[mt][nt][3]));
        }

    // ---- fenced counter: last CTA per Mtile reduces + applies cell ----
    __threadfence();
    __syncthreads();
    __shared__ unsigned s_old;
    if (tid == 0) s_old = atomicAdd(&g_cnt[t * 32 + Mtile], 1u);
    __syncthreads();
    if (s_old != NCH - 1) return;
    __threadfence();

    __nv_bfloat16* __restrict__ hhiW = g_hhi + (size_t)((t + 1) & 1) * (Bn * Hn);
    __nv_bfloat16* __restrict__ hloW = g_hlo + (size_t)((t + 1) & 1) * (Bn * Hn);

    const int jslot = tid & 31;                 // 32 hidden units per Mtile
    const int rg    = tid >> 5;                 // 0..7
    const int j     = Mtile * 32 + jslot;
    const int gcb   = Mtile * 128 + jslot * 4;
    const float b0 = g_bp[gcb + 0], b1 = g_bp[gcb + 1];
    const float b2 = g_bp[gcb + 2], b3 = g_bp[gcb + 3];

#pragma unroll
    for (int half = 0; half < 2; half++) {
        const int r4 = half * 32 + rg * 4;
        float4 gate[4];
        gate[0] = make_float4(b0, b0, b0, b0);
        gate[1] = make_float4(b1, b1, b1, b1);
        gate[2] = make_float4(b2, b2, b2, b2);
        gate[3] = make_float4(b3, b3, b3, b3);
#pragma unroll
        for (int c2 = 0; c2 < NCH; c2++)
#pragma unroll
            for (int q = 0; q < 4; q++) {
                float4 p = __ldcg((const float4*)(
                    g_part + ((size_t)c2 * Gn + gcb + q) * Bn + r4));
                gate[q].x += p.x; gate[q].y += p.y;
                gate[q].z += p.z; gate[q].w += p.w;
            }
#pragma unroll
        for (int e = 0; e < 4; e++) {
            int r = r4 + e;
            float gi = ((const float*)&gate[0])[e];
            float gf = ((const float*)&gate[1])[e];
            float gg = ((const float*)&gate[2])[e];
            float go = ((const float*)&gate[3])[e];
            float iv = 1.0f / (1.0f + expf(-gi));
            float fv = 1.0f / (1.0f + expf(-gf));
            float gv = tanhf(gg);
            float ov = 1.0f / (1.0f + expf(-go));
            int ci = r * Hn + j;
            float cn = fv * __ldcg(g_c + ci) + iv * gv;
            __stcg(g_c + ci, cn);
            float hv = ov * tanhf(cn);
            __nv_bfloat16 hh = __float2bfloat16(hv);
            hhiW[ci] = hh;
            hloW[ci] = __float2bfloat16(hv - __bfloat162float(hh));
            out[((size_t)r * Tn + t) * Hn + j] = hv;
        }
    }
}

// ---------------------------------------------------------------------------
extern "C" void kernel_launch(void* const* d_in, const int* in_sizes, int n_in,
                              void* d_out, int out_size) {
    const float *x = nullptr, *Wx = nullptr, *Wh = nullptr, *b = nullptr;
    for (int i = 0; i < n_in; i++) {
        switch (in_sizes[i]) {
            case Bn * Tn * In: x  = (const float*)d_in[i]; break;  // 8388608
            case In * Gn:      Wx = (const float*)d_in[i]; break;  // 2097152
            case Hn * Gn:      Wh = (const float*)d_in[i]; break;  // 4194304
            case Gn:           b  = (const float*)d_in[i]; break;  // 4096
        }
    }
    float* out = (float*)d_out;

    (void)cudaFuncSetAttribute(gemm_kernel,
                               cudaFuncAttributeMaxDynamicSharedMemorySize,
                               SMEM_TOTAL);

    wprep_kernel<<<dim3(Gn, 6), 256>>>(Wx, Wh, b);
    xprep_kernel<<<8192, 1024>>>(x);

    for (int t = 0; t < Tn; t++) {
        gemm_kernel<<<dim3(32, NCH), 256, SMEM_TOTAL>>>(t, out);
    }
}

// round 10
// speedup vs baseline: 1.6158x; 1.6158x over previous
#include <cuda_runtime.h>
#include <cuda_bf16.h>
#include <stdint.h>
#include <math.h>

// LSTM: B=64, T=256, I=512, H=1024 -> out[b,t,h] fp32
//
// Per step t: gates^T D[gc, r] = sum_k Wt[gc][k] * act[r][k],  K = 1536,
// Wt = [Wh;Wx]^T gate-interleaved (gc = 4j+q), act = [h_t | x_t].
// Precision: bf16 2-term split (hi+lo); 3 HMMA products (hi*hi + hi*lo +
// lo*hi) accumulated in fp32 => rel err ~1e-5.
//
// Structure (proven R7 two-kernel shape):
//   gemm_kernel: grid (32 Mtiles x 4 K-splits) = 128 CTAs, 8 warps, warp tile
//   32gc x 32n, mma.sync m16n8k16.bf16, 3-stage cp.async pipeline.
//   Partials -> g_part[ch][gc][r]. Kernel boundary = coherence point.
//   cell_kernel: reduce 4 partials + bias (fixed order, deterministic),
//   FAST-MATH gates (__expf + __fdividef: 2 MUFU per sigmoid/tanh), write
//   out + re-split h (single h buffer: written by cell t, read by gemm t+1).

#define Bn 64
#define Tn 256
#define In 512
#define Hn 1024
#define Gn 4096
#define Kt 1536
#define NCH 4
#define KCH 384
#define BK 64
#define NCHUNK 6

// stage layout (bytes): WH 0..16K, WL 16K..32K, AH 32K..40K, AL 40K..48K
#define ST_WH 0
#define ST_WL 16384
#define ST_AH 32768
#define ST_AL 40960
#define STAGE_BYTES 49152
#define NSTAGE 3
#define SMEM_TOTAL (NSTAGE * STAGE_BYTES)   // 147456

#define SWZ(o) ((o) ^ (((o) >> 3) & 0x70))

static __device__ __nv_bfloat16 g_Whi[(size_t)Gn * Kt];
static __device__ __nv_bfloat16 g_Wlo[(size_t)Gn * Kt];
static __device__ __nv_bfloat16 g_xhi[(size_t)Bn * Tn * In];
static __device__ __nv_bfloat16 g_xlo[(size_t)Bn * Tn * In];
static __device__ __nv_bfloat16 g_hhi[Bn * Hn];
static __device__ __nv_bfloat16 g_hlo[Bn * Hn];
static __device__ float g_c[Bn * Hn];
static __device__ float g_bp[Gn];
static __device__ float g_part[(size_t)NCH * Gn * Bn];   // [ch][gc][r] 4 MB

// ---------------------------------------------------------------------------
__device__ __forceinline__ uint32_t smem_u32(const void* p) {
    uint32_t a;
    asm("{ .reg .u64 t; cvta.to.shared.u64 t, %1; cvt.u32.u64 %0, t; }"
        : "=r"(a) : "l"(p));
    return a;
}
__device__ __forceinline__ void cpa16(uint32_t dst, const void* src) {
    asm volatile("cp.async.cg.shared.global [%0], [%1], 16;"
                 :: "r"(dst), "l"(src));
}
#define CP_COMMIT() asm volatile("cp.async.commit_group;" ::: "memory")
#define CP_WAIT(n)  asm volatile("cp.async.wait_group %0;" :: "n"(n) : "memory")

__device__ __forceinline__ void ldm_x4(uint32_t a, uint32_t r[4]) {
    asm volatile("ldmatrix.sync.aligned.m8n8.x4.shared.b16 {%0,%1,%2,%3}, [%4];"
                 : "=r"(r[0]), "=r"(r[1]), "=r"(r[2]), "=r"(r[3]) : "r"(a));
}
__device__ __forceinline__ void mma16816(float acc[4], const uint32_t a[4],
                                         uint32_t b0, uint32_t b1) {
    asm volatile(
        "mma.sync.aligned.m16n8k16.row.col.f32.bf16.bf16.f32 "
        "{%0,%1,%2,%3}, {%4,%5,%6,%7}, {%8,%9}, {%0,%1,%2,%3};"
        : "+f"(acc[0]), "+f"(acc[1]), "+f"(acc[2]), "+f"(acc[3])
        : "r"(a[0]), "r"(a[1]), "r"(a[2]), "r"(a[3]), "r"(b0), "r"(b1));
}

// fast gates: 2 MUFU each; saturate correctly (inf denom -> 0 per __fdividef)
__device__ __forceinline__ float fsig(float x) {
    return __fdividef(1.0f, 1.0f + __expf(-x));
}
__device__ __forceinline__ float ftanh(float x) {
    return __fdividef(2.0f, 1.0f + __expf(-2.0f * x)) - 1.0f;
}

// ---------------------------------------------------------------------------
__global__ void wprep_kernel(const float* __restrict__ Wx,
                             const float* __restrict__ Wh,
                             const float* __restrict__ b) {
    int gc = blockIdx.x;
    int k  = blockIdx.y * 256 + threadIdx.x;
    int j = gc >> 2, q = gc & 3;
    int src = q * Hn + j;
    float w = (k < Hn) ? Wh[(size_t)k * Gn + src]
                       : Wx[(size_t)(k - Hn) * Gn + src];
    __nv_bfloat16 hi = __float2bfloat16(w);
    g_Whi[(size_t)gc * Kt + k] = hi;
    g_Wlo[(size_t)gc * Kt + k] = __float2bfloat16(w - __bfloat162float(hi));
    if (k == 0) g_bp[gc] = b[src];
}

// ---------------------------------------------------------------------------
__global__ void xprep_kernel(const float* __restrict__ x) {
    int idx = blockIdx.x * 1024 + threadIdx.x;
    float v = x[idx];
    __nv_bfloat16 hi = __float2bfloat16(v);
    g_xhi[idx] = hi;
    g_xlo[idx] = __float2bfloat16(v - __bfloat162float(hi));
    if (idx < Bn * Hn) {
        g_c[idx] = 0.0f;
        __nv_bfloat16 z = __float2bfloat16(0.0f);
        g_hhi[idx] = z;
        g_hlo[idx] = z;
    }
}

// ---------------------------------------------------------------------------
// gemm: D[128 gc, 64 r] per (Mtile, ch). 8 warps (4 m x 2 n), warp tile
// 32gc x 32n, k-steps of 16 within 6 BK=64 stages, 3-stage cp.async pipeline.
// ---------------------------------------------------------------------------
__global__ __launch_bounds__(256, 1)
void gemm_kernel(int t) {
    extern __shared__ char smem[];
    const uint32_t sb = smem_u32(smem);

    const int tid   = threadIdx.x;
    const int lane  = tid & 31;
    const int warp  = tid >> 5;
    const int wr    = warp & 3;
    const int wc    = warp >> 2;
    const int Mtile = blockIdx.x;
    const int ch    = blockIdx.y;
    const int kBase = ch * KCH;

    auto load_stage = [&](int c) {
        const uint32_t st = sb + (uint32_t)(c % NSTAGE) * STAGE_BYTES;
        const int k0 = kBase + c * BK;
#pragma unroll
        for (int i = 0; i < 4; i++) {
            int l = tid + 256 * i;
            int row = l >> 3;
            int kq = (l & 7) << 3;
            uint32_t off = SWZ((uint32_t)(row * 128 + kq * 2));
            size_t ga = (size_t)(Mtile * 128 + row) * Kt + k0 + kq;
            cpa16(st + ST_WH + off, g_Whi + ga);
            cpa16(st + ST_WL + off, g_Wlo + ga);
        }
#pragma unroll
        for (int i = 0; i < 2; i++) {
            int l = tid + 256 * i;
            int row = l >> 3;
            int kq = (l & 7) << 3;
            uint32_t off = SWZ((uint32_t)(row * 128 + kq * 2));
            int k = k0 + kq;
            const __nv_bfloat16 *ph, *pl;
            if (k < Hn) {
                ph = g_hhi + row * Hn + k;
                pl = g_hlo + row * Hn + k;
            } else {
                size_t xo = ((size_t)row * Tn + t) * In + (k - Hn);
                ph = g_xhi + xo;
                pl = g_xlo + xo;
            }
            cpa16(st + ST_AH + off, ph);
            cpa16(st + ST_AL + off, pl);
        }
        CP_COMMIT();
    };

    float acc[2][4][4];
#pragma unroll
    for (int mt = 0; mt < 2; mt++)
#pragma unroll
        for (int nt = 0; nt < 4; nt++)
#pragma unroll
            for (int e = 0; e < 4; e++) acc[mt][nt][e] = 0.0f;

    const int lm_m = lane >> 3;
    const int lm_r = lane & 7;

    load_stage(0);
    load_stage(1);

#pragma unroll
    for (int c = 0; c < NCHUNK; c++) {
        if (c + 2 < NCHUNK) load_stage(c + 2);
        if (c < NCHUNK - 2)       { CP_WAIT(2); }
        else if (c == NCHUNK - 2) { CP_WAIT(1); }
        else                      { CP_WAIT(0); }
        __syncthreads();

        const uint32_t st = sb + (uint32_t)(c % NSTAGE) * STAGE_BYTES;

#pragma unroll
        for (int ks = 0; ks < 4; ks++) {
            const int kc = ks * 16;
            uint32_t ah[2][4], al[2][4];
#pragma unroll
            for (int mt = 0; mt < 2; mt++) {
                int row = wr * 32 + mt * 16 + (lm_m & 1) * 8 + lm_r;
                int kcol = kc + (lm_m >> 1) * 8;
                uint32_t off = SWZ((uint32_t)(row * 128 + kcol * 2));
                ldm_x4(st + ST_WH + off, ah[mt]);
                ldm_x4(st + ST_WL + off, al[mt]);
            }
            uint32_t bh[4][2], bl[4][2];
#pragma unroll
            for (int np = 0; np < 2; np++) {
                int nrow = wc * 32 + np * 16 + (lm_m >> 1) * 8 + lm_r;
                int kcol = kc + (lm_m & 1) * 8;
                uint32_t off = SWZ((uint32_t)(nrow * 128 + kcol * 2));
                uint32_t rh[4], rl[4];
                ldm_x4(st + ST_AH + off, rh);
                ldm_x4(st + ST_AL + off, rl);
                bh[2 * np][0] = rh[0]; bh[2 * np][1] = rh[1];
                bh[2 * np + 1][0] = rh[2]; bh[2 * np + 1][1] = rh[3];
                bl[2 * np][0] = rl[0]; bl[2 * np][1] = rl[1];
                bl[2 * np + 1][0] = rl[2]; bl[2 * np + 1][1] = rl[3];
            }
#pragma unroll
            for (int mt = 0; mt < 2; mt++)
#pragma unroll
                for (int nt = 0; nt < 4; nt++) {
                    mma16816(acc[mt][nt], ah[mt], bh[nt][0], bh[nt][1]);
                    mma16816(acc[mt][nt], ah[mt], bl[nt][0], bl[nt][1]);
                    mma16816(acc[mt][nt], al[mt], bh[nt][0], bh[nt][1]);
                }
        }
        __syncthreads();
    }

    // epilogue: D frag lane map: g=lane>>2, tq=lane&3
    const int dg = lane >> 2;
    const int dt = lane & 3;
#pragma unroll
    for (int mt = 0; mt < 2; mt++)
#pragma unroll
        for (int nt = 0; nt < 4; nt++) {
            int gc0 = Mtile * 128 + wr * 32 + mt * 16 + dg;
            int r0  = wc * 32 + nt * 8 + 2 * dt;
            float* p0 = g_part + ((size_t)ch * Gn + gc0) * Bn + r0;
            *(float2*)p0 = make_float2(acc[mt][nt][0], acc[mt][nt][1]);
            float* p1 = g_part + ((size_t)ch * Gn + gc0 + 8) * Bn + r0;
            *(float2*)p1 = make_float2(acc[mt][nt][2], acc[mt][nt][3]);
        }
}

// ---------------------------------------------------------------------------
// cell: reduce NCH partials + bias (fixed order), fast-math LSTM cell,
// write out + re-split h. Thread = (4 units per block via jj, r=tid&63).
// ---------------------------------------------------------------------------
__global__ __launch_bounds__(256)
void cell_kernel(int t, float* __restrict__ out) {
    int jj = threadIdx.x >> 6;
    int r  = threadIdx.x & 63;
    int j  = blockIdx.x * 4 + jj;

    float g[4];
#pragma unroll
    for (int q = 0; q < 4; q++) {
        int gc = 4 * j + q;
        float s = 0.0f;
#pragma unroll
        for (int c2 = 0; c2 < NCH; c2++)
            s += g_part[((size_t)c2 * Gn + gc) * Bn + r];
        g[q] = s + g_bp[gc];
    }
    float iv = fsig(g[0]);
    float fv = fsig(g[1]);
    float gv = ftanh(g[2]);
    float ov = fsig(g[3]);

    int ci = r * Hn + j;
    float cn = fv * g_c[ci] + iv * gv;
    g_c[ci] = cn;
    float hv = ov * ftanh(cn);

    __nv_bfloat16 hh = __float2bfloat16(hv);
    g_hhi[ci] = hh;
    g_hlo[ci] = __float2bfloat16(hv - __bfloat162float(hh));
    out[((size_t)r * Tn + t) * Hn + j] = hv;
}

// ---------------------------------------------------------------------------
extern "C" void kernel_launch(void* const* d_in, const int* in_sizes, int n_in,
                              void* d_out, int out_size) {
    const float *x = nullptr, *Wx = nullptr, *Wh = nullptr, *b = nullptr;
    for (int i = 0; i < n_in; i++) {
        switch (in_sizes[i]) {
            case Bn * Tn * In: x  = (const float*)d_in[i]; break;  // 8388608
            case In * Gn:      Wx = (const float*)d_in[i]; break;  // 2097152
            case Hn * Gn:      Wh = (const float*)d_in[i]; break;  // 4194304
            case Gn:           b  = (const float*)d_in[i]; break;  // 4096
        }
    }
    float* out = (float*)d_out;

    (void)cudaFuncSetAttribute(gemm_kernel,
                               cudaFuncAttributeMaxDynamicSharedMemorySize,
                               SMEM_TOTAL);

    wprep_kernel<<<dim3(Gn, 6), 256>>>(Wx, Wh, b);
    xprep_kernel<<<8192, 1024>>>(x);

    for (int t = 0; t < Tn; t++) {
        gemm_kernel<<<dim3(32, NCH), 256, SMEM_TOTAL>>>(t);
        cell_kernel<<<256, 256>>>(t, out);
    }
}

// round 13
// speedup vs baseline: 1.8759x; 1.1610x over previous
#include <cuda_runtime.h>
#include <cuda_bf16.h>
#include <stdint.h>
#include <math.h>

// LSTM: B=64, T=256, I=512, H=1024 -> out[b,t,h] fp32
//
// Per step t: D[r, gc] = sum_k act[r][k] * Wt[gc][k],  K = 1536,
// Wt = [Wh;Wx]^T gate-interleaved (gc = 4j+q), act = [h_t | x_t].
// Precision: bf16 2-term split (hi+lo); 3 HMMA products (a_hi*b_hi +
// a_lo*b_hi + a_hi*b_lo) accumulated in fp32 => rel err ~1e-5.
//
// MMA operand roles: A = act (M = 64 batch rows, 2 warps), B = W (N = 128
// gate-cols, 4 warps) so D is r-major and partials land as [ch][r][gc].
// cell_kernel then reads 4 coalesced float4 per thread (vs 16 scalar loads
// in the gc-major layout) -> latency-bound cell gets ~2.5x faster.
//
//   gemm_kernel: grid (32 Mtiles x 4 K-splits) = 128 CTAs, 8 warps,
//   warp tile 32r x 32gc, mma.sync m16n8k16.bf16, 3-stage cp.async pipeline.
//   cell_kernel: reduce 4 partials + bias (fixed order, deterministic),
//   fast-math gates, write out + re-split h.

#define Bn 64
#define Tn 256
#define In 512
#define Hn 1024
#define Gn 4096
#define Kt 1536
#define NCH 4
#define KCH 384
#define BK 64
#define NCHUNK 6

// stage layout (bytes): WH 0..16K, WL 16K..32K, AH 32K..40K, AL 40K..48K
#define ST_WH 0
#define ST_WL 16384
#define ST_AH 32768
#define ST_AL 40960
#define STAGE_BYTES 49152
#define NSTAGE 3
#define SMEM_TOTAL (NSTAGE * STAGE_BYTES)   // 147456

#define SWZ(o) ((o) ^ (((o) >> 3) & 0x70))

static __device__ __nv_bfloat16 g_Whi[(size_t)Gn * Kt];
static __device__ __nv_bfloat16 g_Wlo[(size_t)Gn * Kt];
static __device__ __nv_bfloat16 g_xhi[(size_t)Bn * Tn * In];
static __device__ __nv_bfloat16 g_xlo[(size_t)Bn * Tn * In];
static __device__ __nv_bfloat16 g_hhi[Bn * Hn];
static __device__ __nv_bfloat16 g_hlo[Bn * Hn];
static __device__ float g_c[Bn * Hn];
static __device__ float g_bp[Gn];
static __device__ float g_part[(size_t)NCH * Bn * Gn];   // [ch][r][gc] 4 MB

// ---------------------------------------------------------------------------
__device__ __forceinline__ uint32_t smem_u32(const void* p) {
    uint32_t a;
    asm("{ .reg .u64 t; cvta.to.shared.u64 t, %1; cvt.u32.u64 %0, t; }"
        : "=r"(a) : "l"(p));
    return a;
}
__device__ __forceinline__ void cpa16(uint32_t dst, const void* src) {
    asm volatile("cp.async.cg.shared.global [%0], [%1], 16;"
                 :: "r"(dst), "l"(src));
}
#define CP_COMMIT() asm volatile("cp.async.commit_group;" ::: "memory")
#define CP_WAIT(n)  asm volatile("cp.async.wait_group %0;" :: "n"(n) : "memory")

__device__ __forceinline__ void ldm_x4(uint32_t a, uint32_t r[4]) {
    asm volatile("ldmatrix.sync.aligned.m8n8.x4.shared.b16 {%0,%1,%2,%3}, [%4];"
                 : "=r"(r[0]), "=r"(r[1]), "=r"(r[2]), "=r"(r[3]) : "r"(a));
}
__device__ __forceinline__ void mma16816(float acc[4], const uint32_t a[4],
                                         uint32_t b0, uint32_t b1) {
    asm volatile(
        "mma.sync.aligned.m16n8k16.row.col.f32.bf16.bf16.f32 "
        "{%0,%1,%2,%3}, {%4,%5,%6,%7}, {%8,%9}, {%0,%1,%2,%3};"
        : "+f"(acc[0]), "+f"(acc[1]), "+f"(acc[2]), "+f"(acc[3])
        : "r"(a[0]), "r"(a[1]), "r"(a[2]), "r"(a[3]), "r"(b0), "r"(b1));
}

// fast gates: 2 MUFU each; saturate correctly at +-inf
__device__ __forceinline__ float fsig(float x) {
    return __fdividef(1.0f, 1.0f + __expf(-x));
}
__device__ __forceinline__ float ftanh(float x) {
    return __fdividef(2.0f, 1.0f + __expf(-2.0f * x)) - 1.0f;
}

// ---------------------------------------------------------------------------
__global__ void wprep_kernel(const float* __restrict__ Wx,
                             const float* __restrict__ Wh,
                             const float* __restrict__ b) {
    int gc = blockIdx.x;
    int k  = blockIdx.y * 256 + threadIdx.x;
    int j = gc >> 2, q = gc & 3;
    int src = q * Hn + j;
    float w = (k < Hn) ? Wh[(size_t)k * Gn + src]
                       : Wx[(size_t)(k - Hn) * Gn + src];
    __nv_bfloat16 hi = __float2bfloat16(w);
    g_Whi[(size_t)gc * Kt + k] = hi;
    g_Wlo[(size_t)gc * Kt + k] = __float2bfloat16(w - __bfloat162float(hi));
    if (k == 0) g_bp[gc] = b[src];
}

// ---------------------------------------------------------------------------
__global__ void xprep_kernel(const float* __restrict__ x) {
    int idx = blockIdx.x * 1024 + threadIdx.x;
    float v = x[idx];
    __nv_bfloat16 hi = __float2bfloat16(v);
    g_xhi[idx] = hi;
    g_xlo[idx] = __float2bfloat16(v - __bfloat162float(hi));
    if (idx < Bn * Hn) {
        g_c[idx] = 0.0f;
        __nv_bfloat16 z = __float2bfloat16(0.0f);
        g_hhi[idx] = z;
        g_hlo[idx] = z;
    }
}

// ---------------------------------------------------------------------------
// gemm: D[64 r, 128 gc] per (Mtile, ch). 8 warps = 2 (M=r) x 4 (N=gc),
// warp tile 32r x 32gc, k-steps of 16 within 6 BK=64 stages, 3-stage pipeline.
// ---------------------------------------------------------------------------
__global__ __launch_bounds__(256, 1)
void gemm_kernel(int t) {
    extern __shared__ char smem[];
    const uint32_t sb = smem_u32(smem);

    const int tid   = threadIdx.x;
    const int lane  = tid & 31;
    const int warp  = tid >> 5;
    const int wr    = warp & 1;          // M (batch rows): 2 warps x 32 r
    const int wc    = warp >> 1;         // N (gate cols):  4 warps x 32 gc
    const int Mtile = blockIdx.x;
    const int ch    = blockIdx.y;
    const int kBase = ch * KCH;

    auto load_stage = [&](int c) {
        const uint32_t st = sb + (uint32_t)(c % NSTAGE) * STAGE_BYTES;
        const int k0 = kBase + c * BK;
#pragma unroll
        for (int i = 0; i < 4; i++) {
            int l = tid + 256 * i;
            int row = l >> 3;
            int kq = (l & 7) << 3;
            uint32_t off = SWZ((uint32_t)(row * 128 + kq * 2));
            size_t ga = (size_t)(Mtile * 128 + row) * Kt + k0 + kq;
            cpa16(st + ST_WH + off, g_Whi + ga);
            cpa16(st + ST_WL + off, g_Wlo + ga);
        }
#pragma unroll
        for (int i = 0; i < 2; i++) {
            int l = tid + 256 * i;
            int row = l >> 3;
            int kq = (l & 7) << 3;
            uint32_t off = SWZ((uint32_t)(row * 128 + kq * 2));
            int k = k0 + kq;
            const __nv_bfloat16 *ph, *pl;
            if (k < Hn) {
                ph = g_hhi + row * Hn + k;
                pl = g_hlo + row * Hn + k;
            } else {
                size_t xo = ((size_t)row * Tn + t) * In + (k - Hn);
                ph = g_xhi + xo;
                pl = g_xlo + xo;
            }
            cpa16(st + ST_AH + off, ph);
            cpa16(st + ST_AL + off, pl);
        }
        CP_COMMIT();
    };

    float acc[2][4][4];
#pragma unroll
    for (int mt = 0; mt < 2; mt++)
#pragma unroll
        for (int nt = 0; nt < 4; nt++)
#pragma unroll
            for (int e = 0; e < 4; e++) acc[mt][nt][e] = 0.0f;

    const int lm_m = lane >> 3;
    const int lm_r = lane & 7;

    load_stage(0);
    load_stage(1);

#pragma unroll
    for (int c = 0; c < NCHUNK; c++) {
        if (c + 2 < NCHUNK) load_stage(c + 2);
        if (c < NCHUNK - 2)       { CP_WAIT(2); }
        else if (c == NCHUNK - 2) { CP_WAIT(1); }
        else                      { CP_WAIT(0); }
        __syncthreads();

        const uint32_t st = sb + (uint32_t)(c % NSTAGE) * STAGE_BYTES;

#pragma unroll
        for (int ks = 0; ks < 4; ks++) {
            const int kc = ks * 16;
            // A fragments from act tile (rows = batch r)
            uint32_t ah[2][4], al[2][4];
#pragma unroll
            for (int mt = 0; mt < 2; mt++) {
                int row = wr * 32 + mt * 16 + (lm_m & 1) * 8 + lm_r;
                int kcol = kc + (lm_m >> 1) * 8;
                uint32_t off = SWZ((uint32_t)(row * 128 + kcol * 2));
                ldm_x4(st + ST_AH + off, ah[mt]);
                ldm_x4(st + ST_AL + off, al[mt]);
            }
            // B fragments from W tile (rows = gate cols gc)
            uint32_t bh[4][2], bl[4][2];
#pragma unroll
            for (int np = 0; np < 2; np++) {
                int nrow = wc * 32 + np * 16 + (lm_m >> 1) * 8 + lm_r;
                int kcol = kc + (lm_m & 1) * 8;
                uint32_t off = SWZ((uint32_t)(nrow * 128 + kcol * 2));
                uint32_t rh[4], rl[4];
                ldm_x4(st + ST_WH + off, rh);
                ldm_x4(st + ST_WL + off, rl);
                bh[2 * np][0] = rh[0]; bh[2 * np][1] = rh[1];
                bh[2 * np + 1][0] = rh[2]; bh[2 * np + 1][1] = rh[3];
                bl[2 * np][0] = rl[0]; bl[2 * np][1] = rl[1];
                bl[2 * np + 1][0] = rl[2]; bl[2 * np + 1][1] = rl[3];
            }
#pragma unroll
            for (int mt = 0; mt < 2; mt++)
#pragma unroll
                for (int nt = 0; nt < 4; nt++) {
                    mma16816(acc[mt][nt], ah[mt], bh[nt][0], bh[nt][1]);
                    mma16816(acc[mt][nt], al[mt], bh[nt][0], bh[nt][1]);
                    mma16816(acc[mt][nt], ah[mt], bl[nt][0], bl[nt][1]);
                }
        }
        __syncthreads();
    }

    // epilogue: D row-major (r, gc): d0,d1 = same r, adjacent gc -> float2.
    const int dg = lane >> 2;            // r offset within 8-row group
    const int dt = lane & 3;             // gc pair index
#pragma unroll
    for (int mt = 0; mt < 2; mt++)
#pragma unroll
        for (int nt = 0; nt < 4; nt++) {
            int r0  = wr * 32 + mt * 16 + dg;
            int gc0 = Mtile * 128 + wc * 32 + nt * 8 + 2 * dt;
            float* p0 = g_part + ((size_t)ch * Bn + r0) * Gn + gc0;
            *(float2*)p0 = make_float2(acc[mt][nt][0], acc[mt][nt][1]);
            float* p1 = g_part + ((size_t)ch * Bn + r0 + 8) * Gn + gc0;
            *(float2*)p1 = make_float2(acc[mt][nt][2], acc[mt][nt][3]);
        }
}

// ---------------------------------------------------------------------------
// cell: thread (r, j): 4 coalesced float4 partial loads (one per chunk,
// fixed order) + bias float4; fast-math LSTM cell; out + re-split h.
// ---------------------------------------------------------------------------
__global__ __launch_bounds__(256)
void cell_kernel(int t, float* __restrict__ out) {
    int w = blockIdx.x * 256 + threadIdx.x;   // 0..65535
    int r = w >> 10;                          // batch row 0..63
    int j = w & 1023;                         // hidden unit

    float4 s = *(const float4*)(g_bp + 4 * j);
#pragma unroll
    for (int c2 = 0; c2 < NCH; c2++) {
        float4 p = *(const float4*)(g_part + ((size_t)c2 * Bn + r) * Gn + 4 * j);
        s.x += p.x; s.y += p.y; s.z += p.z; s.w += p.w;
    }
    float iv = fsig(s.x);
    float fv = fsig(s.y);
    float gv = ftanh(s.z);
    float ov = fsig(s.w);

    int ci = r * Hn + j;
    float cn = fv * g_c[ci] + iv * gv;
    g_c[ci] = cn;
    float hv = ov * ftanh(cn);

    __nv_bfloat16 hh = __float2bfloat16(hv);
    g_hhi[ci] = hh;
    g_hlo[ci] = __float2bfloat16(hv - __bfloat162float(hh));
    out[((size_t)r * Tn + t) * Hn + j] = hv;
}

// ---------------------------------------------------------------------------
extern "C" void kernel_launch(void* const* d_in, const int* in_sizes, int n_in,
                              void* d_out, int out_size) {
    const float *x = nullptr, *Wx = nullptr, *Wh = nullptr, *b = nullptr;
    for (int i = 0; i < n_in; i++) {
        switch (in_sizes[i]) {
            case Bn * Tn * In: x  = (const float*)d_in[i]; break;  // 8388608
            case In * Gn:      Wx = (const float*)d_in[i]; break;  // 2097152
            case Hn * Gn:      Wh = (const float*)d_in[i]; break;  // 4194304
            case Gn:           b  = (const float*)d_in[i]; break;  // 4096
        }
    }
    float* out = (float*)d_out;

    (void)cudaFuncSetAttribute(gemm_kernel,
                               cudaFuncAttributeMaxDynamicSharedMemorySize,
                               SMEM_TOTAL);

    wprep_kernel<<<dim3(Gn, 6), 256>>>(Wx, Wh, b);
    xprep_kernel<<<8192, 1024>>>(x);

    for (int t = 0; t < Tn; t++) {
        gemm_kernel<<<dim3(32, NCH), 256, SMEM_TOTAL>>>(t);
        cell_kernel<<<256, 256>>>(t, out);
    }
}

// round 15
// speedup vs baseline: 1.9025x; 1.0142x over previous
#include <cuda_runtime.h>
#include <cuda_bf16.h>
#include <stdint.h>
#include <math.h>

// LSTM: B=64, T=256, I=512, H=1024 -> out[b,t,h] fp32
//
// Per step t: D[r, gc] = sum_k act[r][k] * Wt[gc][k],  K = 1536,
// Wt = [Wh;Wx]^T gate-interleaved (gc = 4j+q), act = [h_t | x_t].
// Precision: bf16 2-term split (hi+lo); 3 HMMA products (a_hi*b_hi +
// a_lo*b_hi + a_hi*b_lo) accumulated in fp32 => rel err ~6e-6.
//
// MMA roles: A = act (M=64 rows, 2 warps), B = W (N=128 gc, 4 warps) ->
// r-major partials [ch][r][gc]; cell reads 4 coalesced float4 per thread.
//
// R14 deltas vs R13 (2939 us):
//   cell: grid 128 x 512 (single wave on 148 SMs; was 256 CTAs = 2 waves)
//   gemm: 4-stage cp.async pipeline (was 3) — covers L2 latency at 1 CTA/SM

#define Bn 64
#define Tn 256
#define In 512
#define Hn 1024
#define Gn 4096
#define Kt 1536
#define NCH 4
#define KCH 384
#define BK 64
#define NCHUNK 6

// stage layout (bytes): WH 0..16K, WL 16K..32K, AH 32K..40K, AL 40K..48K
#define ST_WH 0
#define ST_WL 16384
#define ST_AH 32768
#define ST_AL 40960
#define STAGE_BYTES 49152
#define NSTAGE 4
#define SMEM_TOTAL (NSTAGE * STAGE_BYTES)   // 196608

#define SWZ(o) ((o) ^ (((o) >> 3) & 0x70))

static __device__ __nv_bfloat16 g_Whi[(size_t)Gn * Kt];
static __device__ __nv_bfloat16 g_Wlo[(size_t)Gn * Kt];
static __device__ __nv_bfloat16 g_xhi[(size_t)Bn * Tn * In];
static __device__ __nv_bfloat16 g_xlo[(size_t)Bn * Tn * In];
static __device__ __nv_bfloat16 g_hhi[Bn * Hn];
static __device__ __nv_bfloat16 g_hlo[Bn * Hn];
static __device__ float g_c[Bn * Hn];
static __device__ float g_bp[Gn];
static __device__ float g_part[(size_t)NCH * Bn * Gn];   // [ch][r][gc] 4 MB

// ---------------------------------------------------------------------------
__device__ __forceinline__ uint32_t smem_u32(const void* p) {
    uint32_t a;
    asm("{ .reg .u64 t; cvta.to.shared.u64 t, %1; cvt.u32.u64 %0, t; }"
        : "=r"(a) : "l"(p));
    return a;
}
__device__ __forceinline__ void cpa16(uint32_t dst, const void* src) {
    asm volatile("cp.async.cg.shared.global [%0], [%1], 16;"
                 :: "r"(dst), "l"(src));
}
#define CP_COMMIT() asm volatile("cp.async.commit_group;" ::: "memory")
#define CP_WAIT(n)  asm volatile("cp.async.wait_group %0;" :: "n"(n) : "memory")

__device__ __forceinline__ void ldm_x4(uint32_t a, uint32_t r[4]) {
    asm volatile("ldmatrix.sync.aligned.m8n8.x4.shared.b16 {%0,%1,%2,%3}, [%4];"
                 : "=r"(r[0]), "=r"(r[1]), "=r"(r[2]), "=r"(r[3]) : "r"(a));
}
__device__ __forceinline__ void mma16816(float acc[4], const uint32_t a[4],
                                         uint32_t b0, uint32_t b1) {
    asm volatile(
        "mma.sync.aligned.m16n8k16.row.col.f32.bf16.bf16.f32 "
        "{%0,%1,%2,%3}, {%4,%5,%6,%7}, {%8,%9}, {%0,%1,%2,%3};"
        : "+f"(acc[0]), "+f"(acc[1]), "+f"(acc[2]), "+f"(acc[3])
        : "r"(a[0]), "r"(a[1]), "r"(a[2]), "r"(a[3]), "r"(b0), "r"(b1));
}

// fast gates: 2 MUFU each; saturate correctly at +-inf
__device__ __forceinline__ float fsig(float x) {
    return __fdividef(1.0f, 1.0f + __expf(-x));
}
__device__ __forceinline__ float ftanh(float x) {
    return __fdividef(2.0f, 1.0f + __expf(-2.0f * x)) - 1.0f;
}

// ---------------------------------------------------------------------------
__global__ void wprep_kernel(const float* __restrict__ Wx,
                             const float* __restrict__ Wh,
                             const float* __restrict__ b) {
    int gc = blockIdx.x;
    int k  = blockIdx.y * 256 + threadIdx.x;
    int j = gc >> 2, q = gc & 3;
    int src = q * Hn + j;
    float w = (k < Hn) ? Wh[(size_t)k * Gn + src]
                       : Wx[(size_t)(k - Hn) * Gn + src];
    __nv_bfloat16 hi = __float2bfloat16(w);
    g_Whi[(size_t)gc * Kt + k] = hi;
    g_Wlo[(size_t)gc * Kt + k] = __float2bfloat16(w - __bfloat162float(hi));
    if (k == 0) g_bp[gc] = b[src];
}

// ---------------------------------------------------------------------------
__global__ void xprep_kernel(const float* __restrict__ x) {
    int idx = blockIdx.x * 1024 + threadIdx.x;
    float v = x[idx];
    __nv_bfloat16 hi = __float2bfloat16(v);
    g_xhi[idx] = hi;
    g_xlo[idx] = __float2bfloat16(v - __bfloat162float(hi));
    if (idx < Bn * Hn) {
        g_c[idx] = 0.0f;
        __nv_bfloat16 z = __float2bfloat16(0.0f);
        g_hhi[idx] = z;
        g_hlo[idx] = z;
    }
}

// ---------------------------------------------------------------------------
// gemm: D[64 r, 128 gc] per (Mtile, ch). 8 warps = 2 (M=r) x 4 (N=gc),
// warp tile 32r x 32gc, k-steps of 16 within 6 BK=64 stages, 4-stage pipeline.
// ---------------------------------------------------------------------------
__global__ __launch_bounds__(256, 1)
void gemm_kernel(int t) {
    extern __shared__ char smem[];
    const uint32_t sb = smem_u32(smem);

    const int tid   = threadIdx.x;
    const int lane  = tid & 31;
    const int warp  = tid >> 5;
    const int wr    = warp & 1;          // M (batch rows): 2 warps x 32 r
    const int wc    = warp >> 1;         // N (gate cols):  4 warps x 32 gc
    const int Mtile = blockIdx.x;
    const int ch    = blockIdx.y;
    const int kBase = ch * KCH;

    auto load_stage = [&](int c) {
        const uint32_t st = sb + (uint32_t)(c % NSTAGE) * STAGE_BYTES;
        const int k0 = kBase + c * BK;
#pragma unroll
        for (int i = 0; i < 4; i++) {
            int l = tid + 256 * i;
            int row = l >> 3;
            int kq = (l & 7) << 3;
            uint32_t off = SWZ((uint32_t)(row * 128 + kq * 2));
            size_t ga = (size_t)(Mtile * 128 + row) * Kt + k0 + kq;
            cpa16(st + ST_WH + off, g_Whi + ga);
            cpa16(st + ST_WL + off, g_Wlo + ga);
        }
#pragma unroll
        for (int i = 0; i < 2; i++) {
            int l = tid + 256 * i;
            int row = l >> 3;
            int kq = (l & 7) << 3;
            uint32_t off = SWZ((uint32_t)(row * 128 + kq * 2));
            int k = k0 + kq;
            const __nv_bfloat16 *ph, *pl;
            if (k < Hn) {
                ph = g_hhi + row * Hn + k;
                pl = g_hlo + row * Hn + k;
            } else {
                size_t xo = ((size_t)row * Tn + t) * In + (k - Hn);
                ph = g_xhi + xo;
                pl = g_xlo + xo;
            }
            cpa16(st + ST_AH + off, ph);
            cpa16(st + ST_AL + off, pl);
        }
        CP_COMMIT();
    };

    float acc[2][4][4];
#pragma unroll
    for (int mt = 0; mt < 2; mt++)
#pragma unroll
        for (int nt = 0; nt < 4; nt++)
#pragma unroll
            for (int e = 0; e < 4; e++) acc[mt][nt][e] = 0.0f;

    const int lm_m = lane >> 3;
    const int lm_r = lane & 7;

    load_stage(0);
    load_stage(1);
    load_stage(2);

#pragma unroll
    for (int c = 0; c < NCHUNK; c++) {
        if (c + 3 < NCHUNK) load_stage(c + 3);
        if (c + 3 < NCHUNK)        { CP_WAIT(3); }
        else if (c == NCHUNK - 3)  { CP_WAIT(2); }
        else if (c == NCHUNK - 2)  { CP_WAIT(1); }
        else                       { CP_WAIT(0); }
        __syncthreads();

        const uint32_t st = sb + (uint32_t)(c % NSTAGE) * STAGE_BYTES;

#pragma unroll
        for (int ks = 0; ks < 4; ks++) {
            const int kc = ks * 16;
            // A fragments from act tile (rows = batch r)
            uint32_t ah[2][4], al[2][4];
#pragma unroll
            for (int mt = 0; mt < 2; mt++) {
                int row = wr * 32 + mt * 16 + (lm_m & 1) * 8 + lm_r;
                int kcol = kc + (lm_m >> 1) * 8;
                uint32_t off = SWZ((uint32_t)(row * 128 + kcol * 2));
                ldm_x4(st + ST_AH + off, ah[mt]);
                ldm_x4(st + ST_AL + off, al[mt]);
            }
            // B fragments from W tile (rows = gate cols gc)
            uint32_t bh[4][2], bl[4][2];
#pragma unroll
            for (int np = 0; np < 2; np++) {
                int nrow = wc * 32 + np * 16 + (lm_m >> 1) * 8 + lm_r;
                int kcol = kc + (lm_m & 1) * 8;
                uint32_t off = SWZ((uint32_t)(nrow * 128 + kcol * 2));
                uint32_t rh[4], rl[4];
                ldm_x4(st + ST_WH + off, rh);
                ldm_x4(st + ST_WL + off, rl);
                bh[2 * np][0] = rh[0]; bh[2 * np][1] = rh[1];
                bh[2 * np + 1][0] = rh[2]; bh[2 * np + 1][1] = rh[3];
                bl[2 * np][0] = rl[0]; bl[2 * np][1] = rl[1];
                bl[2 * np + 1][0] = rl[2]; bl[2 * np + 1][1] = rl[3];
            }
#pragma unroll
            for (int mt = 0; mt < 2; mt++)
#pragma unroll
                for (int nt = 0; nt < 4; nt++) {
                    mma16816(acc[mt][nt], ah[mt], bh[nt][0], bh[nt][1]);
                    mma16816(acc[mt][nt], al[mt], bh[nt][0], bh[nt][1]);
                    mma16816(acc[mt][nt], ah[mt], bl[nt][0], bl[nt][1]);
                }
        }
        __syncthreads();
    }

    // epilogue: D row-major (r, gc): d0,d1 = same r, adjacent gc -> float2.
    const int dg = lane >> 2;            // r offset within 8-row group
    const int dt = lane & 3;             // gc pair index
#pragma unroll
    for (int mt = 0; mt < 2; mt++)
#pragma unroll
        for (int nt = 0; nt < 4; nt++) {
            int r0  = wr * 32 + mt * 16 + dg;
            int gc0 = Mtile * 128 + wc * 32 + nt * 8 + 2 * dt;
            float* p0 = g_part + ((size_t)ch * Bn + r0) * Gn + gc0;
            *(float2*)p0 = make_float2(acc[mt][nt][0], acc[mt][nt][1]);
            float* p1 = g_part + ((size_t)ch * Bn + r0 + 8) * Gn + gc0;
            *(float2*)p1 = make_float2(acc[mt][nt][2], acc[mt][nt][3]);
        }
}

// ---------------------------------------------------------------------------
// cell: thread (r, j): 4 coalesced float4 partial loads (one per chunk,
// fixed order) + bias float4; fast-math LSTM cell; out + re-split h.
// grid 128 x 512 = single wave on 148 SMs.
// ---------------------------------------------------------------------------
__global__ __launch_bounds__(512)
void cell_kernel(int t, float* __restrict__ out) {
    int w = blockIdx.x * 512 + threadIdx.x;   // 0..65535
    int r = w >> 10;                          // batch row 0..63
    int j = w & 1023;                         // hidden unit

    float4 s = *(const float4*)(g_bp + 4 * j);
#pragma unroll
    for (int c2 = 0; c2 < NCH; c2++) {
        float4 p = *(const float4*)(g_part + ((size_t)c2 * Bn + r) * Gn + 4 * j);
        s.x += p.x; s.y += p.y; s.z += p.z; s.w += p.w;
    }
    float iv = fsig(s.x);
    float fv = fsig(s.y);
    float gv = ftanh(s.z);
    float ov = fsig(s.w);

    int ci = r * Hn + j;
    float cn = fv * g_c[ci] + iv * gv;
    g_c[ci] = cn;
    float hv = ov * ftanh(cn);

    __nv_bfloat16 hh = __float2bfloat16(hv);
    g_hhi[ci] = hh;
    g_hlo[ci] = __float2bfloat16(hv - __bfloat162float(hh));
    out[((size_t)r * Tn + t) * Hn + j] = hv;
}

// ---------------------------------------------------------------------------
extern "C" void kernel_launch(void* const* d_in, const int* in_sizes, int n_in,
                              void* d_out, int out_size) {
    const float *x = nullptr, *Wx = nullptr, *Wh = nullptr, *b = nullptr;
    for (int i = 0; i < n_in; i++) {
        switch (in_sizes[i]) {
            case Bn * Tn * In: x  = (const float*)d_in[i]; break;  // 8388608
            case In * Gn:      Wx = (const float*)d_in[i]; break;  // 2097152
            case Hn * Gn:      Wh = (const float*)d_in[i]; break;  // 4194304
            case Gn:           b  = (const float*)d_in[i]; break;  // 4096
        }
    }
    float* out = (float*)d_out;

    (void)cudaFuncSetAttribute(gemm_kernel,
                               cudaFuncAttributeMaxDynamicSharedMemorySize,
                               SMEM_TOTAL);

    wprep_kernel<<<dim3(Gn, 6), 256>>>(Wx, Wh, b);
    xprep_kernel<<<8192, 1024>>>(x);

    for (int t = 0; t < Tn; t++) {
        gemm_kernel<<<dim3(32, NCH), 256, SMEM_TOTAL>>>(t);
        cell_kernel<<<128, 512>>>(t, out);
    }
}